// round 6
// baseline (speedup 1.0000x reference)
#include <cuda_runtime.h>
#include <math.h>

typedef unsigned long long ull;

#define B_  32
#define N_  196
#define C_  32
#define K_  64
#define P_  100

// ---------------- scratch (device globals, no allocation) ----------------
__device__ float g_DS[B_ * N_ * C_];     // diag of Sigma_in, [b][n][c]
__device__ float g_S [B_ * N_ * N_];     // per-batch spatial gram
__device__ float g_G [B_ * P_ * P_];     // patch gram
__device__ float g_DV[B_ * P_ * K_];     // diag_vals
__device__ float g_SP[K_];               // softplus(w_sigma)
__device__ float g_W2[25 * C_ * K_];     // w_mu^2, same layout as w_mu

// ---------------- f32x2 helpers ----------------
__device__ __forceinline__ void unpack2(ull v, float& lo, float& hi) {
    asm("mov.b64 {%0, %1}, %2;" : "=f"(lo), "=f"(hi) : "l"(v));
}
__device__ __forceinline__ void fma2(ull& acc, ull a, ull b) {
    asm("fma.rn.f32x2 %0, %1, %2, %0;" : "+l"(acc) : "l"(a), "l"(b));
}
__device__ __forceinline__ ull pack2(float lo, float hi) {
    ull r; asm("mov.b64 %0, {%1, %2};" : "=l"(r) : "f"(lo), "f"(hi)); return r;
}
__device__ __forceinline__ void stcs4(float4* p, float4 v) {
    asm volatile("st.global.cs.v4.f32 [%0], {%1, %2, %3, %4};"
                 :: "l"(p), "f"(v.x), "f"(v.y), "f"(v.z), "f"(v.w) : "memory");
}

// ---------------- K0: diag gather + softplus + w^2 ----------------
__global__ void k0_prep(const float* __restrict__ Sigma_in,
                        const float* __restrict__ w_sigma,
                        const float* __restrict__ w_mu) {
    int i = blockIdx.x * 256 + threadIdx.x;           // 784*256 = 200704 threads
    if (i < B_ * N_ * C_) {
        int c = i & 31;
        int n = (i >> 5) % N_;
        int b = i / (N_ * C_);
        g_DS[i] = Sigma_in[((b * N_ + n) * N_ + n) * C_ + c];
    }
    if (i < 25 * C_ * K_) {
        float w = w_mu[i];
        g_W2[i] = w * w;
    }
    if (i < K_) g_SP[i] = log1pf(expf(w_sigma[i]));
}

// ---------------- K1: S[b][n1][n2] = sum_c mu[b][n1][c]*mu[b][n2][c] ----------------
__global__ void k1_sgram(const float* __restrict__ mu_in) {
    __shared__ float4 musm[N_ * 9];
    int b   = blockIdx.y;
    int bt  = blockIdx.x;            // n1 tile of 16
    int tid = threadIdx.x;
    const float4* mu4 = (const float4*)mu_in + b * (N_ * C_ / 4);
    for (int idx = tid; idx < N_ * 8; idx += 256)
        musm[(idx >> 3) * 9 + (idx & 7)] = mu4[idx];
    __syncthreads();

    int i1 = tid >> 4, jn2 = tid & 15;
    int n1 = bt * 16 + i1;
    if (n1 < N_) {
        float4 a[8];
#pragma unroll
        for (int j = 0; j < 8; j++) a[j] = musm[n1 * 9 + j];
        for (int n2 = jn2; n2 < N_; n2 += 16) {
            float acc = 0.f;
#pragma unroll
            for (int j = 0; j < 8; j++) {
                float4 bv = musm[n2 * 9 + j];
                acc += a[j].x * bv.x + a[j].y * bv.y + a[j].z * bv.z + a[j].w * bv.w;
            }
            g_S[(b * N_ + n1) * N_ + n2] = acc;
        }
    }
}

// ---------------- K2: G[b][p][q] = sum over 25 taps of S ----------------
__global__ void k2_g() {
    int i = blockIdx.x * 256 + threadIdx.x;
    if (i >= B_ * P_ * P_) return;
    int q = i % 100; int t = i / 100; int p = t % 100; int b = t / 100;
    int pi = p / 10, pj = p % 10, qi = q / 10, qj = q % 10;
    const float* Sb = g_S + b * N_ * N_;
    float s = 0.f;
#pragma unroll
    for (int ki = 0; ki < 5; ki++) {
        int r1 = (pi + ki) * 14 + pj;
        int r2 = (qi + ki) * 14 + qj;
#pragma unroll
        for (int kj = 0; kj < 5; kj++)
            s += Sb[(r1 + kj) * N_ + (r2 + kj)];
    }
    g_G[i] = s;
}

// ---------------- K3: dual conv (mu_out / v1) + trace + diag_vals ----------------
// grid (8, 32): blockIdx.x = pt(0..3) | mset<<2.  160 threads = 5 warps.
//   Each block: one matrix (mu or v1), 25 p (pt*25..pt*25+24), all 64 k.
//   Warp wid handles 5 p; lane owns k-pair (2*lane, 2*lane+1).
//   Region stored DUPLICATED in smem: value v at float2 (v,v) so a broadcast
//   LDS.64 feeds fma.f32x2 directly. Weights via LDG (L1-resident after tap 0).
__global__ __launch_bounds__(160) void k3_conv(const float* __restrict__ mu_in,
                                               const float* __restrict__ w_mu,
                                               float* __restrict__ mu_out) {
    __shared__ __align__(16) float2 Rdup[3136];  // 7 rows x 14 x 32, duplicated

    int bx   = blockIdx.x;
    int pt   = bx & 3;                   // p-tile (25 p each)
    int mset = bx >> 2;                  // 0 = mu conv, 1 = v1 conv
    int b    = blockIdx.y;
    int tid  = threadIdx.x;
    int wid  = tid >> 5;                 // p-group 0..4
    int lane = tid & 31;

    int r0 = (7 * pt + 1) / 3;           // {0,2,5,7}: first input row of window

    {   // duplicated region load: 3136 floats -> 3136 float2
        const float* src = (mset ? (const float*)g_DS : mu_in) + b * 6272 + r0 * 448;
        for (int idx = tid; idx < 3136; idx += 160) {
            float v = __ldg(src + idx);
            Rdup[idx] = make_float2(v, v);
        }
    }
    __syncthreads();

    const float2* Wg = (const float2*)(mset ? g_W2 : w_mu);

    int base[5];
#pragma unroll
    for (int pp = 0; pp < 5; pp++) {
        int p  = pt * 25 + wid * 5 + pp;
        int pi = p / 10, pj = p % 10;
        base[pp] = ((pi - r0) * 14 + pj) * 32;
    }

    ull acc[5];
#pragma unroll
    for (int pp = 0; pp < 5; pp++) acc[pp] = 0ULL;

    for (int tap = 0; tap < 25; tap++) {
        int ki = tap / 5, kj = tap - ki * 5;
        int tofs = (ki * 14 + kj) * 32;
        const float2* wtap = Wg + tap * 1024 + lane;
#pragma unroll 8
        for (int c = 0; c < 32; c++) {
            float2 wv = __ldg(wtap + c * 32);
            ull w = pack2(wv.x, wv.y);
            int ao = tofs + c;
#pragma unroll
            for (int pp = 0; pp < 5; pp++) {
                ull a = *(const ull*)(Rdup + base[pp] + ao);
                fma2(acc[pp], a, w);
            }
        }
    }

    if (mset == 0) {
#pragma unroll
        for (int pp = 0; pp < 5; pp++) {
            int p = pt * 25 + wid * 5 + pp;
            float lo, hi; unpack2(acc[pp], lo, hi);
            float2* dst = (float2*)(mu_out + (b * 100 + p) * 64) + lane;
            *dst = make_float2(lo, hi);
        }
    } else {
        // trace per p (sum of region over 25 taps x 32 c), warp-reduced
        float tr[5];
#pragma unroll
        for (int pp = 0; pp < 5; pp++) {
            float s = 0.f;
#pragma unroll
            for (int tap = 0; tap < 25; tap++) {
                int ki = tap / 5, kj = tap - ki * 5;
                s += Rdup[base[pp] + (ki * 14 + kj) * 32 + lane].x;
            }
#pragma unroll
            for (int o = 16; o > 0; o >>= 1)
                s += __shfl_xor_sync(0xffffffffu, s, o);
            tr[pp] = s;
        }
        float splo = g_SP[2 * lane], sphi = g_SP[2 * lane + 1];
#pragma unroll
        for (int pp = 0; pp < 5; pp++) {
            int p = pt * 25 + wid * 5 + pp;
            float lo, hi; unpack2(acc[pp], lo, hi);
            lo += splo * tr[pp]; hi += sphi * tr[pp];
            float2* dst = (float2*)(g_DV + (b * 100 + p) * 64) + lane;
            *dst = make_float2(lo, hi);
        }
    }
}

// ---------------- K4: Sigma_out writer (streaming, float4 + st.cs) ----------------
__global__ void k4_sigma(float* __restrict__ out) {
    int i = blockIdx.x * 256 + threadIdx.x;    // 5,120,000 float4 units
    int k4 = i & 15;
    int t  = i >> 4;
    int q  = t % 100; int t2 = t / 100; int p = t2 % 100; int b = t2 / 100;

    float g = __ldg(&g_G[(b * 100 + p) * 100 + q]);
    const float4* SP4 = (const float4*)g_SP;
    float4 sp = SP4[k4];
    float4 v;
    v.x = sp.x * g; v.y = sp.y * g; v.z = sp.z * g; v.w = sp.w * g;
    if (p == q) {
        const float4* DV4 = (const float4*)g_DV;
        float4 dv = DV4[(b * 100 + p) * 16 + k4];
        v.x += dv.x; v.y += dv.y; v.z += dv.z; v.w += dv.w;
    }
    if (!isfinite(v.x)) v.x = 0.f;
    if (!isfinite(v.y)) v.y = 0.f;
    if (!isfinite(v.z)) v.z = 0.f;
    if (!isfinite(v.w)) v.w = 0.f;
    if ((q >> 2) == k4) {                       // q == k (only possible for q < 64)
        int r = q & 3;
        if      (r == 0) v.x = fabsf(v.x);
        else if (r == 1) v.y = fabsf(v.y);
        else if (r == 2) v.z = fabsf(v.z);
        else             v.w = fabsf(v.w);
    }
    stcs4(((float4*)out) + 51200 + i, v);       // Sigma_out after mu_out (204800 floats)
}

// ---------------- launch ----------------
extern "C" void kernel_launch(void* const* d_in, const int* in_sizes, int n_in,
                              void* d_out, int out_size) {
    const float* mu_in    = (const float*)d_in[0];
    const float* Sigma_in = (const float*)d_in[1];
    const float* w_mu     = (const float*)d_in[2];
    const float* w_sigma  = (const float*)d_in[3];
    float* out = (float*)d_out;

    k0_prep <<<784, 256>>>(Sigma_in, w_sigma, w_mu);
    k1_sgram<<<dim3(13, 32), 256>>>(mu_in);
    k2_g    <<<1250, 256>>>();
    k3_conv <<<dim3(8, 32), 160>>>(mu_in, w_mu, out);
    k4_sigma<<<20000, 256>>>(out);
}

// round 7
// speedup vs baseline: 1.3526x; 1.3526x over previous
#include <cuda_runtime.h>
#include <math.h>

typedef unsigned long long ull;

#define B_  32
#define N_  196
#define C_  32
#define K_  64
#define P_  100

// ---------------- scratch (device globals, no allocation) ----------------
__device__ float g_DS[B_ * N_ * C_];      // diag of Sigma_in, [b][n][c]
__device__ float g_S [B_ * N_ * N_];      // per-batch spatial gram
__device__ float g_G [B_ * P_ * P_];      // patch gram
__device__ float g_DV[B_ * P_ * K_];      // diag_vals
__device__ float g_SP[K_];                // softplus(w_sigma)
__device__ float g_W2[25 * C_ * K_];      // w_mu^2, same layout as w_mu
__device__ float g_P [10][B_ * P_ * K_];  // conv partials: [mset*5+ki]
__device__ float g_TRP[5][B_ * P_];       // trace partials per ki

// ---------------- f32x2 helpers ----------------
__device__ __forceinline__ void unpack2(ull v, float& lo, float& hi) {
    asm("mov.b64 {%0, %1}, %2;" : "=f"(lo), "=f"(hi) : "l"(v));
}
__device__ __forceinline__ void fma2(ull& acc, ull a, ull b) {
    asm("fma.rn.f32x2 %0, %1, %2, %0;" : "+l"(acc) : "l"(a), "l"(b));
}
__device__ __forceinline__ void stcs4(float4* p, float4 v) {
    asm volatile("st.global.cs.v4.f32 [%0], {%1, %2, %3, %4};"
                 :: "l"(p), "f"(v.x), "f"(v.y), "f"(v.z), "f"(v.w) : "memory");
}

// ---------------- K0: diag gather + softplus + w^2 ----------------
__global__ void k0_prep(const float* __restrict__ Sigma_in,
                        const float* __restrict__ w_sigma,
                        const float* __restrict__ w_mu) {
    int i = blockIdx.x * 256 + threadIdx.x;           // 784*256 = 200704 threads
    if (i < B_ * N_ * C_) {
        int c = i & 31;
        int n = (i >> 5) % N_;
        int b = i / (N_ * C_);
        g_DS[i] = Sigma_in[((b * N_ + n) * N_ + n) * C_ + c];
    }
    if (i < 25 * C_ * K_) {
        float w = w_mu[i];
        g_W2[i] = w * w;
    }
    if (i < K_) g_SP[i] = log1pf(expf(w_sigma[i]));
}

// ---------------- K1: S[b][n1][n2] = sum_c mu[b][n1][c]*mu[b][n2][c] ----------------
__global__ void k1_sgram(const float* __restrict__ mu_in) {
    __shared__ float4 musm[N_ * 9];
    int b   = blockIdx.y;
    int bt  = blockIdx.x;            // n1 tile of 16
    int tid = threadIdx.x;
    const float4* mu4 = (const float4*)mu_in + b * (N_ * C_ / 4);
    for (int idx = tid; idx < N_ * 8; idx += 256)
        musm[(idx >> 3) * 9 + (idx & 7)] = mu4[idx];
    __syncthreads();

    int i1 = tid >> 4, jn2 = tid & 15;
    int n1 = bt * 16 + i1;
    if (n1 < N_) {
        float4 a[8];
#pragma unroll
        for (int j = 0; j < 8; j++) a[j] = musm[n1 * 9 + j];
        for (int n2 = jn2; n2 < N_; n2 += 16) {
            float acc = 0.f;
#pragma unroll
            for (int j = 0; j < 8; j++) {
                float4 bv = musm[n2 * 9 + j];
                acc += a[j].x * bv.x + a[j].y * bv.y + a[j].z * bv.z + a[j].w * bv.w;
            }
            g_S[(b * N_ + n1) * N_ + n2] = acc;
        }
    }
}

// ---------------- K2: G[b][p][q] = sum over 25 taps of S ----------------
__global__ void k2_g() {
    int i = blockIdx.x * 256 + threadIdx.x;
    if (i >= B_ * P_ * P_) return;
    int q = i % 100; int t = i / 100; int p = t % 100; int b = t / 100;
    int pi = p / 10, pj = p % 10, qi = q / 10, qj = q % 10;
    const float* Sb = g_S + b * N_ * N_;
    float s = 0.f;
#pragma unroll
    for (int ki = 0; ki < 5; ki++) {
        int r1 = (pi + ki) * 14 + pj;
        int r2 = (qi + ki) * 14 + qj;
#pragma unroll
        for (int kj = 0; kj < 5; kj++)
            s += Sb[(r1 + kj) * N_ + (r2 + kj)];
    }
    g_G[i] = s;
}

// ---------------- K3: tap-split dual conv, partial sums ----------------
// grid (50, 32): bx = ki*10 + mset*5 + pr2.  128 threads = 4 warps.
//   Block: 5 taps (kernel row ki), 20 p (p-rows 2*pr2, 2*pr2+1), one matrix.
//   Warp wid -> 5 p; lane -> k-pair (2*lane, 2*lane+1).
//   Region (2 input rows) duplicated in smem so broadcast LDS.64 feeds
//   fma.f32x2 directly; tap weights staged in smem (natural float2 pairs).
__global__ __launch_bounds__(128) void k3_conv(const float* __restrict__ mu_in,
                                               const float* __restrict__ w_mu) {
    __shared__ __align__(16) float2 Rdup[896];   // 2 rows x 14 x 32, duplicated
    __shared__ __align__(16) float2 wsm[1024];   // one tap: 32 c x 32 k-pairs

    int bx   = blockIdx.x;
    int pr2  = bx % 5;                 // p-row pair: rows 2*pr2, 2*pr2+1
    int mset = (bx / 5) & 1;           // 0 = mu conv, 1 = v1 conv
    int ki   = bx / 10;                // kernel row
    int b    = blockIdx.y;
    int tid  = threadIdx.x;
    int wid  = tid >> 5;               // 0..3
    int lane = tid & 31;

    {   // region load: rows (2*pr2+ki), (2*pr2+ki+1) -> 896 duplicated float2
        const float* src = (mset ? (const float*)g_DS : mu_in)
                           + b * 6272 + (2 * pr2 + ki) * 448;
        for (int idx = tid; idx < 896; idx += 128) {
            float v = __ldg(src + idx);
            Rdup[idx] = make_float2(v, v);
        }
    }

    const float* Wg = mset ? g_W2 : w_mu;

    int base[5];
#pragma unroll
    for (int pp = 0; pp < 5; pp++) {
        int pit = wid * 5 + pp;                  // 0..19 within tile
        base[pp] = (pit / 10) * 448 + (pit % 10) * 32;
    }

    ull acc[5];
#pragma unroll
    for (int pp = 0; pp < 5; pp++) acc[pp] = 0ULL;

    for (int t = 0; t < 5; t++) {
        __syncthreads();
        {   // stage weights for tap ki*5+t (contiguous 2048-float copy)
            const float4* wg = (const float4*)Wg + (ki * 5 + t) * 512;
            float4* w4 = (float4*)wsm;
#pragma unroll
            for (int r = 0; r < 4; r++) w4[tid + r * 128] = wg[tid + r * 128];
        }
        __syncthreads();
        int tofs = t * 32;                       // kj = t
#pragma unroll 8
        for (int c = 0; c < 32; c++) {
            ull w = *((const ull*)wsm + c * 32 + lane);
#pragma unroll
            for (int pp = 0; pp < 5; pp++) {
                ull a = *(const ull*)(Rdup + base[pp] + tofs + c);
                fma2(acc[pp], a, w);
            }
        }
    }

    // store partials
    float2* Pd = (float2*)g_P[mset * 5 + ki];
#pragma unroll
    for (int pp = 0; pp < 5; pp++) {
        int pit = wid * 5 + pp;
        int p   = (2 * pr2 + pit / 10) * 10 + (pit % 10);
        float lo, hi; unpack2(acc[pp], lo, hi);
        Pd[(b * 100 + p) * 32 + lane] = make_float2(lo, hi);
    }

    if (mset == 1) {
        // trace partial for this ki: sum region over 5 kj x 32 c per p
#pragma unroll
        for (int pp = 0; pp < 5; pp++) {
            float s = 0.f;
#pragma unroll
            for (int kj = 0; kj < 5; kj++)
                s += Rdup[base[pp] + kj * 32 + lane].x;
#pragma unroll
            for (int o = 16; o > 0; o >>= 1)
                s += __shfl_xor_sync(0xffffffffu, s, o);
            if (lane == 0) {
                int pit = wid * 5 + pp;
                int p   = (2 * pr2 + pit / 10) * 10 + (pit % 10);
                g_TRP[ki][b * 100 + p] = s;
            }
        }
    }
}

// ---------------- K3b: combine partials -> mu_out, g_DV ----------------
__global__ void k3b_combine(float* __restrict__ mu_out) {
    int idx = blockIdx.x * 256 + threadIdx.x;    // 102400 float2 slots
    int kp = idx & 31;
    int bp = idx >> 5;
    float2 m = make_float2(0.f, 0.f);
    float2 v = make_float2(0.f, 0.f);
    float tr = 0.f;
#pragma unroll
    for (int j = 0; j < 5; j++) {
        float2 a = ((const float2*)g_P[j])[idx];
        m.x += a.x; m.y += a.y;
        float2 c = ((const float2*)g_P[5 + j])[idx];
        v.x += c.x; v.y += c.y;
        tr += g_TRP[j][bp];
    }
    float2 sp = ((const float2*)g_SP)[kp];
    ((float2*)mu_out)[idx] = m;
    v.x += sp.x * tr; v.y += sp.y * tr;
    ((float2*)g_DV)[idx] = v;
}

// ---------------- K4: Sigma_out writer (streaming, float4 + st.cs) ----------------
__global__ void k4_sigma(float* __restrict__ out) {
    int i = blockIdx.x * 256 + threadIdx.x;    // 5,120,000 float4 units
    int k4 = i & 15;
    int t  = i >> 4;
    int q  = t % 100; int t2 = t / 100; int p = t2 % 100; int b = t2 / 100;

    float g = __ldg(&g_G[(b * 100 + p) * 100 + q]);
    const float4* SP4 = (const float4*)g_SP;
    float4 sp = SP4[k4];
    float4 v;
    v.x = sp.x * g; v.y = sp.y * g; v.z = sp.z * g; v.w = sp.w * g;
    if (p == q) {
        const float4* DV4 = (const float4*)g_DV;
        float4 dv = DV4[(b * 100 + p) * 16 + k4];
        v.x += dv.x; v.y += dv.y; v.z += dv.z; v.w += dv.w;
    }
    if (!isfinite(v.x)) v.x = 0.f;
    if (!isfinite(v.y)) v.y = 0.f;
    if (!isfinite(v.z)) v.z = 0.f;
    if (!isfinite(v.w)) v.w = 0.f;
    if ((q >> 2) == k4) {                       // q == k (only possible for q < 64)
        int r = q & 3;
        if      (r == 0) v.x = fabsf(v.x);
        else if (r == 1) v.y = fabsf(v.y);
        else if (r == 2) v.z = fabsf(v.z);
        else             v.w = fabsf(v.w);
    }
    stcs4(((float4*)out) + 51200 + i, v);       // Sigma_out after mu_out (204800 floats)
}

// ---------------- launch ----------------
extern "C" void kernel_launch(void* const* d_in, const int* in_sizes, int n_in,
                              void* d_out, int out_size) {
    const float* mu_in    = (const float*)d_in[0];
    const float* Sigma_in = (const float*)d_in[1];
    const float* w_mu     = (const float*)d_in[2];
    const float* w_sigma  = (const float*)d_in[3];
    float* out = (float*)d_out;

    k0_prep    <<<784, 256>>>(Sigma_in, w_sigma, w_mu);
    k1_sgram   <<<dim3(13, 32), 256>>>(mu_in);
    k2_g       <<<1250, 256>>>();
    k3_conv    <<<dim3(50, 32), 128>>>(mu_in, w_mu);
    k3b_combine<<<400, 256>>>(out);
    k4_sigma   <<<20000, 256>>>(out);
}